// round 6
// baseline (speedup 1.0000x reference)
#include <cuda_runtime.h>
#include <cuda_bf16.h>
#include <cstdint>

// Problem dims (fixed per reference)
#define BB 4
#define TT 1024
#define SS 1024
#define CC 1024
#define HH 16
#define DD 64
#define BT (BB * TT)   // 4096

// ---------------------------------------------------------------------------
// Scratch (allocation-free rule: __device__ globals)
// ---------------------------------------------------------------------------
__device__ float g_Q[BB * HH * TT * DD];     // [B,H,T,D] f32
__device__ float g_K[BB * HH * SS * DD];
__device__ float g_V[BB * HH * SS * DD];
__device__ float g_att[BB * TT * HH * DD];   // [B,T,H,D] == [4096,1024] f32

// Split-bf16 operand storage.
// A rows: [0,4096) = x ; [4096,8192) = y_enc ; [8192,12288) = att
__device__ __nv_bfloat16 g_Ahi[12288 * 1024];
__device__ __nv_bfloat16 g_Alo[12288 * 1024];
// B rows ([n][k], K-major): [0,1024)=Wq^T, [1024,2048)=Wk^T, [2048,3072)=Wv^T,
// [3072,4096)=Wo
__device__ __nv_bfloat16 g_Bhi[4096 * 1024];
__device__ __nv_bfloat16 g_Blo[4096 * 1024];

// ---------------------------------------------------------------------------
// mma.sync m16n8k16 bf16 (baseline sm_80 PTX -> HMMA, no 'a' feature needed)
// ---------------------------------------------------------------------------
__device__ __forceinline__ void mma16816(float* d, const uint32_t* a,
                                         const uint32_t* b) {
    asm volatile(
        "mma.sync.aligned.m16n8k16.row.col.f32.bf16.bf16.f32 "
        "{%0,%1,%2,%3}, {%4,%5,%6,%7}, {%8,%9}, {%0,%1,%2,%3};"
        : "+f"(d[0]), "+f"(d[1]), "+f"(d[2]), "+f"(d[3])
        : "r"(a[0]), "r"(a[1]), "r"(a[2]), "r"(a[3]), "r"(b[0]), "r"(b[1]));
}

// ---- packed f32x2 helpers (attn kernel) -----------------------------------
__device__ __forceinline__ unsigned long long splat2(float v) {
    unsigned long long r;
    asm("mov.b64 %0, {%1, %1};" : "=l"(r) : "r"(__float_as_uint(v)));
    return r;
}
__device__ __forceinline__ void fma2(unsigned long long& d,
                                     unsigned long long a, unsigned long long b) {
    asm("fma.rn.f32x2 %0, %1, %2, %3;" : "=l"(d) : "l"(a), "l"(b), "l"(d));
}
__device__ __forceinline__ void mul2(unsigned long long& d,
                                     unsigned long long a, unsigned long long b) {
    asm("mul.rn.f32x2 %0, %1, %2;" : "=l"(d) : "l"(a), "l"(b));
}
__device__ __forceinline__ float2 unpack2(unsigned long long p) {
    unsigned int lo, hi;
    asm("mov.b64 {%0, %1}, %2;" : "=r"(lo), "=r"(hi) : "l"(p));
    return make_float2(__uint_as_float(lo), __uint_as_float(hi));
}

// ---------------------------------------------------------------------------
// Conversion: f32 -> (hi, lo) bf16, elementwise (vec4)
// ---------------------------------------------------------------------------
__global__ __launch_bounds__(256) void conv_split(
    const float* __restrict__ in, __nv_bfloat16* __restrict__ hi,
    __nv_bfloat16* __restrict__ lo, int n4)
{
    int i = blockIdx.x * blockDim.x + threadIdx.x;
    if (i >= n4) return;
    float4 v = reinterpret_cast<const float4*>(in)[i];
    __nv_bfloat16 h0 = __float2bfloat16(v.x);
    __nv_bfloat16 h1 = __float2bfloat16(v.y);
    __nv_bfloat16 h2 = __float2bfloat16(v.z);
    __nv_bfloat16 h3 = __float2bfloat16(v.w);
    __nv_bfloat16 l0 = __float2bfloat16(v.x - __bfloat162float(h0));
    __nv_bfloat16 l1 = __float2bfloat16(v.y - __bfloat162float(h1));
    __nv_bfloat16 l2 = __float2bfloat16(v.z - __bfloat162float(h2));
    __nv_bfloat16 l3 = __float2bfloat16(v.w - __bfloat162float(h3));
    __nv_bfloat162* hp = reinterpret_cast<__nv_bfloat162*>(hi);
    __nv_bfloat162* lp = reinterpret_cast<__nv_bfloat162*>(lo);
    __nv_bfloat162 a; a.x = h0; a.y = h1;
    __nv_bfloat162 b; b.x = h2; b.y = h3;
    hp[i * 2 + 0] = a; hp[i * 2 + 1] = b;
    __nv_bfloat162 c; c.x = l0; c.y = l1;
    __nv_bfloat162 d; d.x = l2; d.y = l3;
    lp[i * 2 + 0] = c; lp[i * 2 + 1] = d;
}

// Transpose-convert W [H,C,D] -> B rows (h*64+d)[k], split bf16
__global__ __launch_bounds__(256) void conv_wT(
    const float* __restrict__ W, __nv_bfloat16* __restrict__ hi,
    __nv_bfloat16* __restrict__ lo, int rowbase)
{
    int o = blockIdx.x * blockDim.x + threadIdx.x;
    if (o >= HH * DD * CC) return;
    int k  = o & 1023;
    int nd = o >> 10;          // h*64 + d
    int h = nd >> 6, d = nd & 63;
    float v = W[((size_t)h << 16) + ((size_t)k << 6) + d];
    __nv_bfloat16 hv = __float2bfloat16(v);
    float lvf = v - __bfloat162float(hv);
    size_t oi = ((size_t)(rowbase + nd) << 10) + k;
    hi[oi] = hv;
    lo[oi] = __float2bfloat16(lvf);
}

// ---------------------------------------------------------------------------
// Split-bf16 HMMA GEMM: D[128 x 64] = A[128 x 1024] * B[64 x 1024]^T
// mode 0: QKV proj (gy 0..47: type=gy>>4, head=gy&15), store to [B,H,T,D]
// mode 1: outproj  (gy 0..15), store row-major + bias
// 8 warps: warp (wm = wid&3, wn = wid>>2) computes 32(m) x 32(n).
// smem per stage (bf16 elems, row stride 40 = conflict-free frag LDS):
//   Ahi[128*40] | Alo[128*40] | Bhi[64*40] | Blo[64*40]  = 15360 elems
// double buffered -> 61440 bytes.
// ---------------------------------------------------------------------------
#define LDA 40
#define STG_ELEMS (128 * LDA * 2 + 64 * LDA * 2)   // 15360

__global__ __launch_bounds__(256) void gemm_mma(
    int mode,
    const __nv_bfloat16* __restrict__ Ahi, const __nv_bfloat16* __restrict__ Alo,
    const __nv_bfloat16* __restrict__ Bhi, const __nv_bfloat16* __restrict__ Blo,
    const float* __restrict__ bo,
    float* __restrict__ Qo, float* __restrict__ Ko, float* __restrict__ Vo,
    float* __restrict__ Oout)
{
    extern __shared__ __nv_bfloat16 sb[];
    const int tid  = threadIdx.x;
    const int wid  = tid >> 5;
    const int lane = tid & 31;
    const int gg   = lane >> 2;     // group id 0..7
    const int tig  = lane & 3;
    const int wm   = wid & 3;
    const int wn   = wid >> 2;

    const int m0 = blockIdx.x * 128;
    const int gy = blockIdx.y;

    int a_base, b_row;
    if (mode == 0) {
        a_base = ((gy >> 4) == 0) ? 0 : 4096;
        b_row  = gy * 64;
    } else {
        a_base = 8192;
        b_row  = 3072 + gy * 64;
    }

    // global load indices
    const int ar = tid >> 2;             // A row per p-slice: ar, ar+64
    const int ac = (tid & 3) * 8;        // bf16 col within 32-chunk
    const int br = tid >> 2;             // B row 0..63
    const size_t agoff0 = ((size_t)(a_base + m0 + ar) << 10) + ac;
    const size_t agoff1 = ((size_t)(a_base + m0 + ar + 64) << 10) + ac;
    const size_t bgoff  = ((size_t)(b_row + br) << 10) + ac;

    float acc[2][4][4];
#pragma unroll
    for (int mt = 0; mt < 2; mt++)
#pragma unroll
        for (int nt = 0; nt < 4; nt++)
#pragma unroll
            for (int q = 0; q < 4; q++) acc[mt][nt][q] = 0.f;

    uint4 ra_h[2], ra_l[2], rb_h, rb_l;

    // prefetch stage 0
    ra_h[0] = *reinterpret_cast<const uint4*>(Ahi + agoff0);
    ra_h[1] = *reinterpret_cast<const uint4*>(Ahi + agoff1);
    ra_l[0] = *reinterpret_cast<const uint4*>(Alo + agoff0);
    ra_l[1] = *reinterpret_cast<const uint4*>(Alo + agoff1);
    rb_h    = *reinterpret_cast<const uint4*>(Bhi + bgoff);
    rb_l    = *reinterpret_cast<const uint4*>(Blo + bgoff);

    // store stage 0
    {
        __nv_bfloat16* s = sb;   // stage 0
        *reinterpret_cast<uint4*>(s + (size_t)ar * LDA + ac)               = ra_h[0];
        *reinterpret_cast<uint4*>(s + (size_t)(ar + 64) * LDA + ac)        = ra_h[1];
        *reinterpret_cast<uint4*>(s + 128 * LDA + (size_t)ar * LDA + ac)        = ra_l[0];
        *reinterpret_cast<uint4*>(s + 128 * LDA + (size_t)(ar + 64) * LDA + ac) = ra_l[1];
        *reinterpret_cast<uint4*>(s + 256 * LDA + (size_t)br * LDA + ac)        = rb_h;
        *reinterpret_cast<uint4*>(s + 320 * LDA + (size_t)br * LDA + ac)        = rb_l;
    }
    __syncthreads();

    for (int s = 0; s < 32; s++) {
        const int kc = (s + 1) * 32;
        if (s < 31) {
            ra_h[0] = *reinterpret_cast<const uint4*>(Ahi + agoff0 + kc);
            ra_h[1] = *reinterpret_cast<const uint4*>(Ahi + agoff1 + kc);
            ra_l[0] = *reinterpret_cast<const uint4*>(Alo + agoff0 + kc);
            ra_l[1] = *reinterpret_cast<const uint4*>(Alo + agoff1 + kc);
            rb_h    = *reinterpret_cast<const uint4*>(Bhi + bgoff + kc);
            rb_l    = *reinterpret_cast<const uint4*>(Blo + bgoff + kc);
        }

        const __nv_bfloat16* As_h = sb + (size_t)(s & 1) * STG_ELEMS;
        const __nv_bfloat16* As_l = As_h + 128 * LDA;
        const __nv_bfloat16* Bs_h = As_h + 256 * LDA;
        const __nv_bfloat16* Bs_l = As_h + 320 * LDA;

#pragma unroll
        for (int ko2 = 0; ko2 < 2; ko2++) {
            const int ko = ko2 * 16 + 2 * tig;
            uint32_t ah[2][4], al[2][4], bh[4][2], bl[4][2];
#pragma unroll
            for (int mt = 0; mt < 2; mt++) {
                const int rb2 = wm * 32 + mt * 16 + gg;
                const __nv_bfloat16* ph = As_h + rb2 * LDA + ko;
                const __nv_bfloat16* pl = As_l + rb2 * LDA + ko;
                ah[mt][0] = *reinterpret_cast<const uint32_t*>(ph);
                ah[mt][1] = *reinterpret_cast<const uint32_t*>(ph + 8 * LDA);
                ah[mt][2] = *reinterpret_cast<const uint32_t*>(ph + 8);
                ah[mt][3] = *reinterpret_cast<const uint32_t*>(ph + 8 * LDA + 8);
                al[mt][0] = *reinterpret_cast<const uint32_t*>(pl);
                al[mt][1] = *reinterpret_cast<const uint32_t*>(pl + 8 * LDA);
                al[mt][2] = *reinterpret_cast<const uint32_t*>(pl + 8);
                al[mt][3] = *reinterpret_cast<const uint32_t*>(pl + 8 * LDA + 8);
            }
#pragma unroll
            for (int nt = 0; nt < 4; nt++) {
                const int nb = wn * 32 + nt * 8 + gg;
                const __nv_bfloat16* ph = Bs_h + nb * LDA + ko;
                const __nv_bfloat16* pl = Bs_l + nb * LDA + ko;
                bh[nt][0] = *reinterpret_cast<const uint32_t*>(ph);
                bh[nt][1] = *reinterpret_cast<const uint32_t*>(ph + 8);
                bl[nt][0] = *reinterpret_cast<const uint32_t*>(pl);
                bl[nt][1] = *reinterpret_cast<const uint32_t*>(pl + 8);
            }
#pragma unroll
            for (int mt = 0; mt < 2; mt++)
#pragma unroll
                for (int nt = 0; nt < 4; nt++) {
                    mma16816(acc[mt][nt], ah[mt], bh[nt]);
                    mma16816(acc[mt][nt], ah[mt], bl[nt]);
                    mma16816(acc[mt][nt], al[mt], bh[nt]);
                }
        }

        if (s < 31) {
            __nv_bfloat16* d = sb + (size_t)((s + 1) & 1) * STG_ELEMS;
            *reinterpret_cast<uint4*>(d + (size_t)ar * LDA + ac)               = ra_h[0];
            *reinterpret_cast<uint4*>(d + (size_t)(ar + 64) * LDA + ac)        = ra_h[1];
            *reinterpret_cast<uint4*>(d + 128 * LDA + (size_t)ar * LDA + ac)        = ra_l[0];
            *reinterpret_cast<uint4*>(d + 128 * LDA + (size_t)(ar + 64) * LDA + ac) = ra_l[1];
            *reinterpret_cast<uint4*>(d + 256 * LDA + (size_t)br * LDA + ac)        = rb_h;
            *reinterpret_cast<uint4*>(d + 320 * LDA + (size_t)br * LDA + ac)        = rb_l;
            __syncthreads();
        }
    }

    // epilogue
    if (mode == 0) {
        const int type = gy >> 4, h = gy & 15;
        float* Out = (type == 0) ? Qo : (type == 1) ? Ko : Vo;
#pragma unroll
        for (int mt = 0; mt < 2; mt++)
#pragma unroll
            for (int half = 0; half < 2; half++) {
                const int m = m0 + wm * 32 + mt * 16 + gg + half * 8;
                const int b = m >> 10, t = m & 1023;
                float* orow = Out + ((((size_t)(b * HH + h)) * TT + t) << 6);
#pragma unroll
                for (int nt = 0; nt < 4; nt++) {
                    const int col = wn * 32 + nt * 8 + 2 * tig;
                    *reinterpret_cast<float2*>(orow + col) =
                        make_float2(acc[mt][nt][half * 2 + 0],
                                    acc[mt][nt][half * 2 + 1]);
                }
            }
    } else {
#pragma unroll
        for (int mt = 0; mt < 2; mt++)
#pragma unroll
            for (int half = 0; half < 2; half++) {
                const int m = m0 + wm * 32 + mt * 16 + gg + half * 8;
                float* orow = Oout + ((size_t)m << 10) + gy * 64;
#pragma unroll
                for (int nt = 0; nt < 4; nt++) {
                    const int col = wn * 32 + nt * 8 + 2 * tig;
                    float2 bv = *reinterpret_cast<const float2*>(bo + gy * 64 + col);
                    *reinterpret_cast<float2*>(orow + col) =
                        make_float2(acc[mt][nt][half * 2 + 0] + bv.x,
                                    acc[mt][nt][half * 2 + 1] + bv.y);
                }
            }
    }
}

// ---------------------------------------------------------------------------
// Flash attention (FFMA2 SIMT): grid (T/128, B*H), 256 threads
// ---------------------------------------------------------------------------
__global__ __launch_bounds__(256) void attn_kernel(
    const float* __restrict__ Q, const float* __restrict__ K,
    const float* __restrict__ V, float* __restrict__ Oatt)
{
    extern __shared__ float sm[];
    float* Qt = sm;                  // [64 c][132 r]
    float* Kt = Qt + 64 * 132;       // [64 c][68 key]
    float* Vs = Kt + 64 * 68;        // [64 key][68 d]
    float* Ps = Vs + 64 * 68;        // [128 q][68 key]

    const int bh = blockIdx.y;
    const int q0 = blockIdx.x * 128;
    const float* Qb = Q + ((size_t)bh * TT + q0) * DD;
    const float* Kb = K + (size_t)bh * SS * DD;
    const float* Vb = V + (size_t)bh * SS * DD;

    const int tid = threadIdx.x;
    const int tx = tid & 15;
    const int ty = tid >> 4;

#pragma unroll
    for (int p = 0; p < 8; p++) {
        int fq = tid + p * 256;
        int row = fq >> 4;
        int cq  = (fq & 15) * 4;
        float4 v = *reinterpret_cast<const float4*>(&Qb[(size_t)row * DD + cq]);
        Qt[(cq + 0) * 132 + row] = v.x;
        Qt[(cq + 1) * 132 + row] = v.y;
        Qt[(cq + 2) * 132 + row] = v.z;
        Qt[(cq + 3) * 132 + row] = v.w;
    }

    unsigned long long acc2[8][2];
#pragma unroll
    for (int i = 0; i < 8; i++) { acc2[i][0] = 0ull; acc2[i][1] = 0ull; }
    float mi[8], li[8];
#pragma unroll
    for (int i = 0; i < 8; i++) { mi[i] = -1e30f; li[i] = 0.f; }
    const float scale = 0.03125f;

    for (int s0 = 0; s0 < SS; s0 += 64) {
        __syncthreads();
#pragma unroll
        for (int p = 0; p < 4; p++) {
            int fq = tid + p * 256;
            int key = fq >> 4;
            int cq  = (fq & 15) * 4;
            float4 kv = *reinterpret_cast<const float4*>(&Kb[(size_t)(s0 + key) * DD + cq]);
            Kt[(cq + 0) * 68 + key] = kv.x;
            Kt[(cq + 1) * 68 + key] = kv.y;
            Kt[(cq + 2) * 68 + key] = kv.z;
            Kt[(cq + 3) * 68 + key] = kv.w;
            float4 vv = *reinterpret_cast<const float4*>(&Vb[(size_t)(s0 + key) * DD + cq]);
            *reinterpret_cast<float4*>(&Vs[key * 68 + cq]) = vv;
        }
        __syncthreads();

        unsigned long long s2[8][2];
#pragma unroll
        for (int i = 0; i < 8; i++) { s2[i][0] = 0ull; s2[i][1] = 0ull; }
#pragma unroll 8
        for (int c = 0; c < 64; c++) {
            ulonglong2 kp = *reinterpret_cast<const ulonglong2*>(&Kt[c * 68 + tx * 4]);
            float4 qa = *reinterpret_cast<const float4*>(&Qt[c * 132 + ty * 8]);
            float4 qb2 = *reinterpret_cast<const float4*>(&Qt[c * 132 + ty * 8 + 4]);
            float qq[8] = {qa.x, qa.y, qa.z, qa.w, qb2.x, qb2.y, qb2.z, qb2.w};
#pragma unroll
            for (int i = 0; i < 8; i++) {
                unsigned long long qs = splat2(qq[i]);
                fma2(s2[i][0], qs, kp.x);
                fma2(s2[i][1], qs, kp.y);
            }
        }

#pragma unroll
        for (int i = 0; i < 8; i++) {
            float2 sa = unpack2(s2[i][0]);
            float2 sb2 = unpack2(s2[i][1]);
            float s0v = sa.x * scale, s1v = sa.y * scale;
            float s2v = sb2.x * scale, s3v = sb2.y * scale;
            float mx = fmaxf(fmaxf(s0v, s1v), fmaxf(s2v, s3v));
            mx = fmaxf(mx, __shfl_xor_sync(0xffffffffu, mx, 1));
            mx = fmaxf(mx, __shfl_xor_sync(0xffffffffu, mx, 2));
            mx = fmaxf(mx, __shfl_xor_sync(0xffffffffu, mx, 4));
            mx = fmaxf(mx, __shfl_xor_sync(0xffffffffu, mx, 8));
            float mn = fmaxf(mi[i], mx);
            float corr = __expf(mi[i] - mn);
            mi[i] = mn;
            float p0 = __expf(s0v - mn);
            float p1 = __expf(s1v - mn);
            float p2 = __expf(s2v - mn);
            float p3 = __expf(s3v - mn);
            float ps = (p0 + p1) + (p2 + p3);
            ps += __shfl_xor_sync(0xffffffffu, ps, 1);
            ps += __shfl_xor_sync(0xffffffffu, ps, 2);
            ps += __shfl_xor_sync(0xffffffffu, ps, 4);
            ps += __shfl_xor_sync(0xffffffffu, ps, 8);
            li[i] = li[i] * corr + ps;
            unsigned long long cs = splat2(corr);
            mul2(acc2[i][0], acc2[i][0], cs);
            mul2(acc2[i][1], acc2[i][1], cs);
            *reinterpret_cast<float4*>(&Ps[(ty * 8 + i) * 68 + tx * 4]) =
                make_float4(p0, p1, p2, p3);
        }
        __syncwarp();

#pragma unroll 4
        for (int k4i = 0; k4i < 16; k4i++) {
            int key = k4i * 4;
            ulonglong2 v0 = *reinterpret_cast<const ulonglong2*>(&Vs[(key + 0) * 68 + tx * 4]);
            ulonglong2 v1 = *reinterpret_cast<const ulonglong2*>(&Vs[(key + 1) * 68 + tx * 4]);
            ulonglong2 v2 = *reinterpret_cast<const ulonglong2*>(&Vs[(key + 2) * 68 + tx * 4]);
            ulonglong2 v3 = *reinterpret_cast<const ulonglong2*>(&Vs[(key + 3) * 68 + tx * 4]);
#pragma unroll
            for (int i = 0; i < 8; i++) {
                float4 p4 = *reinterpret_cast<const float4*>(&Ps[(ty * 8 + i) * 68 + key]);
                unsigned long long ps0 = splat2(p4.x);
                fma2(acc2[i][0], ps0, v0.x);
                fma2(acc2[i][1], ps0, v0.y);
                unsigned long long ps1 = splat2(p4.y);
                fma2(acc2[i][0], ps1, v1.x);
                fma2(acc2[i][1], ps1, v1.y);
                unsigned long long ps2 = splat2(p4.z);
                fma2(acc2[i][0], ps2, v2.x);
                fma2(acc2[i][1], ps2, v2.y);
                unsigned long long ps3 = splat2(p4.w);
                fma2(acc2[i][0], ps3, v3.x);
                fma2(acc2[i][1], ps3, v3.y);
            }
        }
        __syncwarp();
    }

    const int b  = bh >> 4;
    const int h_ = bh & 15;
#pragma unroll
    for (int i = 0; i < 8; i++) {
        int t = q0 + ty * 8 + i;
        float inv = 1.0f / li[i];
        float2 a0 = unpack2(acc2[i][0]);
        float2 a1 = unpack2(acc2[i][1]);
        float* op = Oatt + (((size_t)(b * TT + t) * HH + h_) * DD) + tx * 4;
        *reinterpret_cast<float4*>(op) =
            make_float4(a0.x * inv, a0.y * inv, a1.x * inv, a1.y * inv);
    }
}

// ---------------------------------------------------------------------------
extern "C" void kernel_launch(void* const* d_in, const int* in_sizes, int n_in,
                              void* d_out, int out_size)
{
    const float* x     = (const float*)d_in[0];
    const float* y_enc = (const float*)d_in[1];
    const float* Wq    = (const float*)d_in[2];
    const float* Wk    = (const float*)d_in[3];
    const float* Wv    = (const float*)d_in[4];
    const float* Wo    = (const float*)d_in[5];
    const float* bo    = (const float*)d_in[6];
    float* out = (float*)d_out;

    float *pQ, *pK, *pV, *pA;
    __nv_bfloat16 *pAhi, *pAlo, *pBhi, *pBlo;
    cudaGetSymbolAddress((void**)&pQ, g_Q);
    cudaGetSymbolAddress((void**)&pK, g_K);
    cudaGetSymbolAddress((void**)&pV, g_V);
    cudaGetSymbolAddress((void**)&pA, g_att);
    cudaGetSymbolAddress((void**)&pAhi, g_Ahi);
    cudaGetSymbolAddress((void**)&pAlo, g_Alo);
    cudaGetSymbolAddress((void**)&pBhi, g_Bhi);
    cudaGetSymbolAddress((void**)&pBlo, g_Blo);

    const int gemm_smem = STG_ELEMS * 2 * (int)sizeof(__nv_bfloat16);  // 61440
    cudaFuncSetAttribute(gemm_mma, cudaFuncAttributeMaxDynamicSharedMemorySize,
                         gemm_smem);
    const int attn_smem = (64 * 132 + 64 * 68 + 64 * 68 + 128 * 68) * (int)sizeof(float);
    cudaFuncSetAttribute(attn_kernel, cudaFuncAttributeMaxDynamicSharedMemorySize,
                         attn_smem);

    const size_t ROW = 1024;
    conv_split<<<4096, 256>>>(x,     pAhi,              pAlo,              BT * 1024 / 4);
    conv_split<<<4096, 256>>>(y_enc, pAhi + 4096 * ROW, pAlo + 4096 * ROW, BT * 1024 / 4);
    conv_wT<<<4096, 256>>>(Wq, pBhi, pBlo, 0);
    conv_wT<<<4096, 256>>>(Wk, pBhi, pBlo, 1024);
    conv_wT<<<4096, 256>>>(Wv, pBhi, pBlo, 2048);
    conv_split<<<1024, 256>>>(Wo, pBhi + 3072 * ROW, pBlo + 3072 * ROW, CC * CC / 4);

    dim3 pg(BT / 128, 48);
    gemm_mma<<<pg, 256, gemm_smem>>>(0, pAhi, pAlo, pBhi, pBlo, bo,
                                     pQ, pK, pV, out);

    dim3 ag(TT / 128, BB * HH);
    attn_kernel<<<ag, 256, attn_smem>>>(pQ, pK, pV, pA);

    conv_split<<<4096, 256>>>(pA, pAhi + 8192 * ROW, pAlo + 8192 * ROW, BT * 1024 / 4);
    dim3 og(BT / 128, 16);
    gemm_mma<<<og, 256, gemm_smem>>>(1, pAhi, pAlo, pBhi, pBlo, bo,
                                     pQ, pK, pV, out);
}

// round 7
// speedup vs baseline: 1.2631x; 1.2631x over previous
#include <cuda_runtime.h>

// Problem dims (fixed per reference)
#define BB 4
#define TT 1024
#define SS 1024
#define CC 1024
#define HH 16
#define DD 64
#define BT (BB * TT)   // 4096

// Scratch buffers (allocation-free rule: __device__ globals)
__device__ float g_Q[BB * HH * TT * DD];     // [B,H,T,D]
__device__ float g_K[BB * HH * SS * DD];     // [B,H,S,D]
__device__ float g_V[BB * HH * SS * DD];     // [B,H,S,D]
__device__ float g_att[BB * TT * HH * DD];   // [B,T,H,D] == [4096, 1024]

// ---- packed f32x2 helpers (FFMA2 path; ptxas never emits from C++) --------
__device__ __forceinline__ unsigned long long splat2(float v) {
    unsigned long long r;
    asm("mov.b64 %0, {%1, %1};" : "=l"(r) : "r"(__float_as_uint(v)));
    return r;
}
__device__ __forceinline__ void fma2(unsigned long long& d,
                                     unsigned long long a, unsigned long long b) {
    asm("fma.rn.f32x2 %0, %1, %2, %3;" : "=l"(d) : "l"(a), "l"(b), "l"(d));
}
__device__ __forceinline__ void mul2(unsigned long long& d,
                                     unsigned long long a, unsigned long long b) {
    asm("mul.rn.f32x2 %0, %1, %2;" : "=l"(d) : "l"(a), "l"(b));
}
__device__ __forceinline__ float2 unpack2(unsigned long long p) {
    unsigned int lo, hi;
    asm("mov.b64 {%0, %1}, %2;" : "=r"(lo), "=r"(hi) : "l"(p));
    return make_float2(__uint_as_float(lo), __uint_as_float(hi));
}

// ---------------------------------------------------------------------------
// Fused QKV projection: Out[b,h,t,d] = sum_c X[b,t,c] * W[h,c,d]
// grid: (BT/128, HH/2, 3), block 256. Tile 128(m) x 128(n = 2 heads), BK=8.
// Double-buffered smem + register prefetch -> one sync per chunk.
// ---------------------------------------------------------------------------
__global__ __launch_bounds__(256, 2) void qkv_proj_kernel(
    const float* __restrict__ x,     // [BT, C]
    const float* __restrict__ y_enc, // [BT, C]
    const float* __restrict__ Wq, const float* __restrict__ Wk,
    const float* __restrict__ Wv,
    float* __restrict__ Qo, float* __restrict__ Ko, float* __restrict__ Vo)
{
    __shared__ float As[2][8][132];   // [buf][k][m]
    __shared__ float Bs[2][8][132];   // [buf][k][n]

    const int z = blockIdx.z;
    const float* X   = (z == 0) ? x  : y_enc;
    const float* W   = (z == 0) ? Wq : (z == 1) ? Wk : Wv;
    float*       Out = (z == 0) ? Qo : (z == 1) ? Ko : Vo;

    const int m0 = blockIdx.x * 128;
    const int h0 = blockIdx.y * 2;

    const int tid = threadIdx.x;
    const int tx = tid & 15;
    const int ty = tid >> 4;

    const int arow = tid >> 1;
    const int akq  = (tid & 1) * 4;
    const int bk = tid >> 5;
    const int bn = (tid & 31) * 4;
    const int bh = h0 + (bn >> 6);
    const int bd = bn & 63;

    const float* Xa = X + (size_t)(m0 + arow) * CC + akq;
    const float* Wb = W + ((size_t)bh * CC + bk) * DD + bd;

    unsigned long long acc2[8][4];
#pragma unroll
    for (int i = 0; i < 8; i++)
#pragma unroll
        for (int j = 0; j < 4; j++) acc2[i][j] = 0ull;

    // prefetch + store chunk 0
    float4 av = *reinterpret_cast<const float4*>(Xa);
    float4 bv = *reinterpret_cast<const float4*>(Wb);
    As[0][akq + 0][arow] = av.x;
    As[0][akq + 1][arow] = av.y;
    As[0][akq + 2][arow] = av.z;
    As[0][akq + 3][arow] = av.w;
    *reinterpret_cast<float4*>(&Bs[0][bk][bn]) = bv;
    __syncthreads();

    for (int it = 0; it < 128; it++) {
        if (it < 127) {
            av = *reinterpret_cast<const float4*>(Xa + (it + 1) * 8);
            bv = *reinterpret_cast<const float4*>(Wb + (size_t)(it + 1) * 8 * DD);
        }
        const float (*A)[132] = As[it & 1];
        const float (*B)[132] = Bs[it & 1];
#pragma unroll
        for (int kk = 0; kk < 8; kk++) {
            float4 a0 = *reinterpret_cast<const float4*>(&A[kk][ty * 8]);
            float4 a1 = *reinterpret_cast<const float4*>(&A[kk][ty * 8 + 4]);
            ulonglong2 bp0 = *reinterpret_cast<const ulonglong2*>(&B[kk][tx * 4]);
            ulonglong2 bp1 = *reinterpret_cast<const ulonglong2*>(&B[kk][64 + tx * 4]);
            unsigned long long bb2[4] = {bp0.x, bp0.y, bp1.x, bp1.y};
            float aa[8] = {a0.x, a0.y, a0.z, a0.w, a1.x, a1.y, a1.z, a1.w};
#pragma unroll
            for (int i = 0; i < 8; i++) {
                unsigned long long as = splat2(aa[i]);
#pragma unroll
                for (int j = 0; j < 4; j++) fma2(acc2[i][j], as, bb2[j]);
            }
        }
        if (it < 127) {
            const int nb = (it + 1) & 1;
            As[nb][akq + 0][arow] = av.x;
            As[nb][akq + 1][arow] = av.y;
            As[nb][akq + 2][arow] = av.z;
            As[nb][akq + 3][arow] = av.w;
            *reinterpret_cast<float4*>(&Bs[nb][bk][bn]) = bv;
            __syncthreads();
        }
    }

#pragma unroll
    for (int i = 0; i < 8; i++) {
        int m = m0 + ty * 8 + i;
        int b = m >> 10;
        int t = m & 1023;
        float2 p0 = unpack2(acc2[i][0]);
        float2 p1 = unpack2(acc2[i][1]);
        float2 p2 = unpack2(acc2[i][2]);
        float2 p3 = unpack2(acc2[i][3]);
        float* o0 = Out + (((size_t)(b * HH + h0)     * TT + t) * DD) + tx * 4;
        float* o1 = Out + (((size_t)(b * HH + h0 + 1) * TT + t) * DD) + tx * 4;
        *reinterpret_cast<float4*>(o0) = make_float4(p0.x, p0.y, p1.x, p1.y);
        *reinterpret_cast<float4*>(o1) = make_float4(p2.x, p2.y, p3.x, p3.y);
    }
}

// ---------------------------------------------------------------------------
// Flash attention: grid (T/128, B*H), block 256. K/V register prefetch.
// ---------------------------------------------------------------------------
__global__ __launch_bounds__(256, 2) void attn_kernel(
    const float* __restrict__ Q, const float* __restrict__ K,
    const float* __restrict__ V, float* __restrict__ Oatt)
{
    extern __shared__ float sm[];
    float* Qt = sm;                  // [64 c][132 r]
    float* Kt = Qt + 64 * 132;       // [64 c][68 key]
    float* Vs = Kt + 64 * 68;        // [64 key][68 d]
    float* Ps = Vs + 64 * 68;        // [128 q][68 key]

    const int bh = blockIdx.y;
    const int q0 = blockIdx.x * 128;
    const float* Qb = Q + ((size_t)bh * TT + q0) * DD;
    const float* Kb = K + (size_t)bh * SS * DD;
    const float* Vb = V + (size_t)bh * SS * DD;

    const int tid = threadIdx.x;
    const int tx = tid & 15;
    const int ty = tid >> 4;

#pragma unroll
    for (int p = 0; p < 8; p++) {
        int fq = tid + p * 256;
        int row = fq >> 4;
        int cq  = (fq & 15) * 4;
        float4 v = *reinterpret_cast<const float4*>(&Qb[(size_t)row * DD + cq]);
        Qt[(cq + 0) * 132 + row] = v.x;
        Qt[(cq + 1) * 132 + row] = v.y;
        Qt[(cq + 2) * 132 + row] = v.z;
        Qt[(cq + 3) * 132 + row] = v.w;
    }

    unsigned long long acc2[8][2];
#pragma unroll
    for (int i = 0; i < 8; i++) { acc2[i][0] = 0ull; acc2[i][1] = 0ull; }
    float mi[8], li[8];
#pragma unroll
    for (int i = 0; i < 8; i++) { mi[i] = -1e30f; li[i] = 0.f; }
    const float scale = 0.03125f;

    // prefetch K/V tile 0 into registers
    float4 kvr[4], vvr[4];
#pragma unroll
    for (int p = 0; p < 4; p++) {
        int fq = tid + p * 256;
        int key = fq >> 4;
        int cq  = (fq & 15) * 4;
        kvr[p] = *reinterpret_cast<const float4*>(&Kb[(size_t)key * DD + cq]);
        vvr[p] = *reinterpret_cast<const float4*>(&Vb[(size_t)key * DD + cq]);
    }

    for (int s0 = 0; s0 < SS; s0 += 64) {
        __syncthreads();   // previous tile's smem reads complete
#pragma unroll
        for (int p = 0; p < 4; p++) {
            int fq = tid + p * 256;
            int key = fq >> 4;
            int cq  = (fq & 15) * 4;
            Kt[(cq + 0) * 68 + key] = kvr[p].x;
            Kt[(cq + 1) * 68 + key] = kvr[p].y;
            Kt[(cq + 2) * 68 + key] = kvr[p].z;
            Kt[(cq + 3) * 68 + key] = kvr[p].w;
            *reinterpret_cast<float4*>(&Vs[key * 68 + cq]) = vvr[p];
        }
        __syncthreads();

        // prefetch next tile (latency hidden under compute below)
        if (s0 + 64 < SS) {
#pragma unroll
            for (int p = 0; p < 4; p++) {
                int fq = tid + p * 256;
                int key = (fq >> 4) + s0 + 64;
                int cq  = (fq & 15) * 4;
                kvr[p] = *reinterpret_cast<const float4*>(&Kb[(size_t)key * DD + cq]);
                vvr[p] = *reinterpret_cast<const float4*>(&Vb[(size_t)key * DD + cq]);
            }
        }

        unsigned long long s2[8][2];
#pragma unroll
        for (int i = 0; i < 8; i++) { s2[i][0] = 0ull; s2[i][1] = 0ull; }
#pragma unroll 8
        for (int c = 0; c < 64; c++) {
            ulonglong2 kp = *reinterpret_cast<const ulonglong2*>(&Kt[c * 68 + tx * 4]);
            float4 qa = *reinterpret_cast<const float4*>(&Qt[c * 132 + ty * 8]);
            float4 qb2 = *reinterpret_cast<const float4*>(&Qt[c * 132 + ty * 8 + 4]);
            float qq[8] = {qa.x, qa.y, qa.z, qa.w, qb2.x, qb2.y, qb2.z, qb2.w};
#pragma unroll
            for (int i = 0; i < 8; i++) {
                unsigned long long qs = splat2(qq[i]);
                fma2(s2[i][0], qs, kp.x);
                fma2(s2[i][1], qs, kp.y);
            }
        }

#pragma unroll
        for (int i = 0; i < 8; i++) {
            float2 sa = unpack2(s2[i][0]);
            float2 sb2 = unpack2(s2[i][1]);
            float s0v = sa.x * scale, s1v = sa.y * scale;
            float s2v = sb2.x * scale, s3v = sb2.y * scale;
            float mx = fmaxf(fmaxf(s0v, s1v), fmaxf(s2v, s3v));
            mx = fmaxf(mx, __shfl_xor_sync(0xffffffffu, mx, 1));
            mx = fmaxf(mx, __shfl_xor_sync(0xffffffffu, mx, 2));
            mx = fmaxf(mx, __shfl_xor_sync(0xffffffffu, mx, 4));
            mx = fmaxf(mx, __shfl_xor_sync(0xffffffffu, mx, 8));
            float mn = fmaxf(mi[i], mx);
            float corr = __expf(mi[i] - mn);
            mi[i] = mn;
            float p0 = __expf(s0v - mn);
            float p1 = __expf(s1v - mn);
            float p2 = __expf(s2v - mn);
            float p3 = __expf(s3v - mn);
            float ps = (p0 + p1) + (p2 + p3);
            ps += __shfl_xor_sync(0xffffffffu, ps, 1);
            ps += __shfl_xor_sync(0xffffffffu, ps, 2);
            ps += __shfl_xor_sync(0xffffffffu, ps, 4);
            ps += __shfl_xor_sync(0xffffffffu, ps, 8);
            li[i] = li[i] * corr + ps;
            unsigned long long cs = splat2(corr);
            mul2(acc2[i][0], acc2[i][0], cs);
            mul2(acc2[i][1], acc2[i][1], cs);
            *reinterpret_cast<float4*>(&Ps[(ty * 8 + i) * 68 + tx * 4]) =
                make_float4(p0, p1, p2, p3);
        }
        __syncwarp();

#pragma unroll 4
        for (int k4i = 0; k4i < 16; k4i++) {
            int key = k4i * 4;
            ulonglong2 v0 = *reinterpret_cast<const ulonglong2*>(&Vs[(key + 0) * 68 + tx * 4]);
            ulonglong2 v1 = *reinterpret_cast<const ulonglong2*>(&Vs[(key + 1) * 68 + tx * 4]);
            ulonglong2 v2 = *reinterpret_cast<const ulonglong2*>(&Vs[(key + 2) * 68 + tx * 4]);
            ulonglong2 v3 = *reinterpret_cast<const ulonglong2*>(&Vs[(key + 3) * 68 + tx * 4]);
#pragma unroll
            for (int i = 0; i < 8; i++) {
                float4 p4 = *reinterpret_cast<const float4*>(&Ps[(ty * 8 + i) * 68 + key]);
                unsigned long long ps0 = splat2(p4.x);
                fma2(acc2[i][0], ps0, v0.x);
                fma2(acc2[i][1], ps0, v0.y);
                unsigned long long ps1 = splat2(p4.y);
                fma2(acc2[i][0], ps1, v1.x);
                fma2(acc2[i][1], ps1, v1.y);
                unsigned long long ps2 = splat2(p4.z);
                fma2(acc2[i][0], ps2, v2.x);
                fma2(acc2[i][1], ps2, v2.y);
                unsigned long long ps3 = splat2(p4.w);
                fma2(acc2[i][0], ps3, v3.x);
                fma2(acc2[i][1], ps3, v3.y);
            }
        }
        __syncwarp();
    }

    const int b  = bh >> 4;
    const int h_ = bh & 15;
#pragma unroll
    for (int i = 0; i < 8; i++) {
        int t = q0 + ty * 8 + i;
        float inv = 1.0f / li[i];
        float2 a0 = unpack2(acc2[i][0]);
        float2 a1 = unpack2(acc2[i][1]);
        float* op = Oatt + (((size_t)(b * TT + t) * HH + h_) * DD) + tx * 4;
        *reinterpret_cast<float4*>(op) =
            make_float4(a0.x * inv, a0.y * inv, a1.x * inv, a1.y * inv);
    }
}

// ---------------------------------------------------------------------------
// Output projection: Out[m,n] = sum_k A[m,k] * Wo[n,k] + bo[n]
// grid: (BT/128, C/128), block 256. Double-buffered BK=8.
// ---------------------------------------------------------------------------
__global__ __launch_bounds__(256, 2) void outproj_kernel(
    const float* __restrict__ A,    // [4096, 1024]
    const float* __restrict__ Wo,   // [C, C], used as Wo[n][k]
    const float* __restrict__ bo,   // [C]
    float* __restrict__ Out)        // [4096, 1024]
{
    __shared__ float As[2][8][132];
    __shared__ float Bs[2][8][132];

    const int m0 = blockIdx.x * 128;
    const int n0 = blockIdx.y * 128;
    const int tid = threadIdx.x;
    const int tx = tid & 15;
    const int ty = tid >> 4;

    const int arow = tid >> 1;
    const int akq  = (tid & 1) * 4;

    const float* Aa = A  + (size_t)(m0 + arow) * CC + akq;
    const float* Wb = Wo + (size_t)(n0 + arow) * CC + akq;

    unsigned long long acc2[8][4];
#pragma unroll
    for (int i = 0; i < 8; i++)
#pragma unroll
        for (int j = 0; j < 4; j++) acc2[i][j] = 0ull;

    float4 av = *reinterpret_cast<const float4*>(Aa);
    float4 bv = *reinterpret_cast<const float4*>(Wb);
    As[0][akq + 0][arow] = av.x;
    As[0][akq + 1][arow] = av.y;
    As[0][akq + 2][arow] = av.z;
    As[0][akq + 3][arow] = av.w;
    Bs[0][akq + 0][arow] = bv.x;
    Bs[0][akq + 1][arow] = bv.y;
    Bs[0][akq + 2][arow] = bv.z;
    Bs[0][akq + 3][arow] = bv.w;
    __syncthreads();

    for (int it = 0; it < 128; it++) {
        if (it < 127) {
            av = *reinterpret_cast<const float4*>(Aa + (it + 1) * 8);
            bv = *reinterpret_cast<const float4*>(Wb + (it + 1) * 8);
        }
        const float (*Ap)[132] = As[it & 1];
        const float (*Bp)[132] = Bs[it & 1];
#pragma unroll
        for (int kk = 0; kk < 8; kk++) {
            float4 a0 = *reinterpret_cast<const float4*>(&Ap[kk][ty * 8]);
            float4 a1 = *reinterpret_cast<const float4*>(&Ap[kk][ty * 8 + 4]);
            ulonglong2 bp0 = *reinterpret_cast<const ulonglong2*>(&Bp[kk][tx * 4]);
            ulonglong2 bp1 = *reinterpret_cast<const ulonglong2*>(&Bp[kk][64 + tx * 4]);
            unsigned long long bb2[4] = {bp0.x, bp0.y, bp1.x, bp1.y};
            float aa[8] = {a0.x, a0.y, a0.z, a0.w, a1.x, a1.y, a1.z, a1.w};
#pragma unroll
            for (int i = 0; i < 8; i++) {
                unsigned long long as = splat2(aa[i]);
#pragma unroll
                for (int j = 0; j < 4; j++) fma2(acc2[i][j], as, bb2[j]);
            }
        }
        if (it < 127) {
            const int nb = (it + 1) & 1;
            As[nb][akq + 0][arow] = av.x;
            As[nb][akq + 1][arow] = av.y;
            As[nb][akq + 2][arow] = av.z;
            As[nb][akq + 3][arow] = av.w;
            Bs[nb][akq + 0][arow] = bv.x;
            Bs[nb][akq + 1][arow] = bv.y;
            Bs[nb][akq + 2][arow] = bv.z;
            Bs[nb][akq + 3][arow] = bv.w;
            __syncthreads();
        }
    }

    float4 bias0 = *reinterpret_cast<const float4*>(&bo[n0 + tx * 4]);
    float4 bias1 = *reinterpret_cast<const float4*>(&bo[n0 + 64 + tx * 4]);
#pragma unroll
    for (int i = 0; i < 8; i++) {
        int m = m0 + ty * 8 + i;
        float2 p0 = unpack2(acc2[i][0]);
        float2 p1 = unpack2(acc2[i][1]);
        float2 p2 = unpack2(acc2[i][2]);
        float2 p3 = unpack2(acc2[i][3]);
        float* o0 = Out + (size_t)m * CC + n0 + tx * 4;
        float* o1 = Out + (size_t)m * CC + n0 + 64 + tx * 4;
        *reinterpret_cast<float4*>(o0) = make_float4(p0.x + bias0.x, p0.y + bias0.y,
                                                     p1.x + bias0.z, p1.y + bias0.w);
        *reinterpret_cast<float4*>(o1) = make_float4(p2.x + bias1.x, p2.y + bias1.y,
                                                     p3.x + bias1.z, p3.y + bias1.w);
    }
}

// ---------------------------------------------------------------------------
extern "C" void kernel_launch(void* const* d_in, const int* in_sizes, int n_in,
                              void* d_out, int out_size)
{
    const float* x     = (const float*)d_in[0];
    const float* y_enc = (const float*)d_in[1];
    const float* Wq    = (const float*)d_in[2];
    const float* Wk    = (const float*)d_in[3];
    const float* Wv    = (const float*)d_in[4];
    const float* Wo    = (const float*)d_in[5];
    const float* bo    = (const float*)d_in[6];
    float* out = (float*)d_out;

    float *pQ, *pK, *pV, *pA;
    cudaGetSymbolAddress((void**)&pQ, g_Q);
    cudaGetSymbolAddress((void**)&pK, g_K);
    cudaGetSymbolAddress((void**)&pV, g_V);
    cudaGetSymbolAddress((void**)&pA, g_att);

    const int attn_smem = (64 * 132 + 64 * 68 + 64 * 68 + 128 * 68) * (int)sizeof(float);
    cudaFuncSetAttribute(attn_kernel, cudaFuncAttributeMaxDynamicSharedMemorySize,
                         attn_smem);

    dim3 pg(BT / 128, HH / 2, 3);
    qkv_proj_kernel<<<pg, 256>>>(x, y_enc, Wq, Wk, Wv, pQ, pK, pV);

    dim3 ag(TT / 128, BB * HH);
    attn_kernel<<<ag, 256, attn_smem>>>(pQ, pK, pV, pA);

    dim3 og(BT / 128, CC / 128);
    outproj_kernel<<<og, 256>>>(pA, Wo, bo, out);
}